// round 5
// baseline (speedup 1.0000x reference)
#include <cuda_runtime.h>
#include <math.h>

#define N_MOL  2048
#define P_PRO  2048
#define HID    64
#define HEADS  16
#define NGRAPH 64
#define NB     256          // counting-sort bins (== NTHR)
#define NBLK   128          // 16 heads x 8 row-groups
#define NTHR   256

// ---- scratch (no allocation allowed) ----
__device__ float2 g_mol2[HEADS][N_MOL];   // (a_mol, exp(a_mol))
__device__ float2 g_pro2[HEADS][P_PRO];   // (a_pro, exp(a_pro))
__device__ float  g_ys[NGRAPH * HEADS];
__device__ int    g_headdone[HEADS];      // per-head producer counters (self-reset)
__device__ int    g_done;                 // head blocks finished (self-reset)

struct SmemB {
    float  bufA[P_PRO];      // raw a_pro -> later y_atom
    float  bufE[P_PRO];      // raw exp(a_pro)
    float  bufB[P_PRO];      // bin-grouped values
    float  bufC[P_PRO];      // bin-grouped exp(values)
    int    bs[N_MOL];        // batch ids
    int    hist[NB];
    int    cnt[NB];
    int    binStart[NB + 1];
    float  prefExp[NB];      // sum exp over bins < k
    float  sufVal[NB + 1];   // sum val over bins >= k
    float  redmn[8], redmx[8];
    int    iwarp[8];
    double dwarpE[8], dwarpV[8];
    float  mnv, mxv;
    int    flag;
};
struct SmemA { float Wc[2 * HID]; };      // one head's weight column (128 floats)
union SmemU { SmemA a; SmemB b; };

__device__ __forceinline__ int bin_of(float v, float mn, float inv) {
    // no-FMA-contraction form so all call sites compute identically
    int b = (int)(__fmul_rn(__fsub_rn(v, mn), inv));
    return b < 0 ? 0 : (b > NB - 1 ? NB - 1 : b);
}

__global__ __launch_bounds__(NTHR, 1)
void fused_kernel(const float* __restrict__ mol,
                  const float* __restrict__ pro,
                  const float* __restrict__ Wmu,
                  const float* __restrict__ bmu,
                  const float* __restrict__ W1,
                  const float* __restrict__ b1,
                  const float* __restrict__ W2,
                  const float* __restrict__ b2,
                  const int*   __restrict__ batch32,
                  float* __restrict__ out) {
    __shared__ SmemU sm;
    int tid  = threadIdx.x;
    int lane = tid & 31;
    int wrp  = tid >> 5;
    int h    = blockIdx.x & 15;   // head
    int g    = blockIdx.x >> 4;   // row-group 0..7 (512 rows each)

    // ===== Phase A: block (h,g) projects 512 rows for head h, stores (a, e^a) =====
    if (tid < 2 * HID) sm.a.Wc[tid] = Wmu[tid * HEADS + h];
    __syncthreads();
    {
        bool is_mol = (g < 4);                 // rows [512g,512g+512) uniform half
        int  quad   = tid & 3;                 // 16-float segment of the row
        int  rloc   = tid >> 2;                // 0..63 within pass
        const float* srcbase = is_mol ? mol : pro;
        int  rowoff = is_mol ? g * 512 : (g - 4) * 512;
        const float* wseg = sm.a.Wc + quad * 16 + (is_mol ? 0 : HID);
        float bias = is_mol ? bmu[h] : 0.0f;
        float2* dst = is_mol ? g_mol2[h] : g_pro2[h];
#pragma unroll 1
        for (int p = 0; p < 8; p++) {
            int r = rowoff + p * 64 + rloc;
            const float* src = srcbase + r * HID + quad * 16;
            float acc = 0.0f;
#pragma unroll
            for (int q = 0; q < 4; q++) {
                float4 v = *(const float4*)(src + 4 * q);
                acc += v.x * wseg[4*q] + v.y * wseg[4*q+1]
                     + v.z * wseg[4*q+2] + v.w * wseg[4*q+3];
            }
            acc += __shfl_xor_sync(0xffffffffu, acc, 1);
            acc += __shfl_xor_sync(0xffffffffu, acc, 2);
            if (quad == 0) {
                float a = acc + bias;
                dst[r] = make_float2(a, expf(a));
            }
        }
    }
    __threadfence();
    __syncthreads();
    if (tid == 0) atomicAdd(&g_headdone[h], 1);
    if (g != 0) return;                        // producers exit

    // ===== head-block h waits for its 7 sibling producers (+itself) =====
    if (tid == 0) {
        while (atomicAdd(&g_headdone[h], 0) < 8) {}
        atomicExch(&g_headdone[h], 0);         // reset for next replay
        __threadfence();
    }
    __syncthreads();

    // ===== Phase B: per-head pipeline (no expf anywhere below) =====
    float mn = 1e30f, mx = -1e30f;
    for (int i = tid; i < P_PRO; i += NTHR) {
        float2 ae = g_pro2[h][i];
        sm.b.bufA[i] = ae.x;
        sm.b.bufE[i] = ae.y;
        mn = fminf(mn, ae.x); mx = fmaxf(mx, ae.x);
    }
    for (int i = tid; i < N_MOL; i += NTHR) sm.b.bs[i] = batch32[i];
    sm.b.hist[tid] = 0;
    sm.b.cnt[tid]  = 0;
    if (tid == 0) sm.b.flag = 0;
#pragma unroll
    for (int o = 16; o > 0; o >>= 1) {
        mn = fminf(mn, __shfl_xor_sync(0xffffffffu, mn, o));
        mx = fmaxf(mx, __shfl_xor_sync(0xffffffffu, mx, o));
    }
    if (lane == 0) { sm.b.redmn[wrp] = mn; sm.b.redmx[wrp] = mx; }
    __syncthreads();
    if (tid == 0) {
        float a = sm.b.redmn[0], b = sm.b.redmx[0];
#pragma unroll
        for (int i = 1; i < NTHR / 32; i++) {
            a = fminf(a, sm.b.redmn[i]); b = fmaxf(b, sm.b.redmx[i]);
        }
        sm.b.mnv = a; sm.b.mxv = b;
    }
    // int64 detection: sorted int32 word stream is monotone; int64's is not
    for (int i = tid; i < N_MOL - 1; i += NTHR)
        if (sm.b.bs[i] > sm.b.bs[i + 1]) sm.b.flag = 1;
    __syncthreads();
    if (sm.b.flag) {  // int64: take low word of each element
        for (int i = tid; i < N_MOL; i += NTHR) sm.b.bs[i] = batch32[2 * i];
    }
    float mnv = sm.b.mnv;
    float inv = (sm.b.mxv > mnv) ? (float)NB / (sm.b.mxv - mnv) : 0.0f;

    // histogram
    for (int i = tid; i < P_PRO; i += NTHR)
        atomicAdd(&sm.b.hist[bin_of(sm.b.bufA[i], mnv, inv)], 1);
    __syncthreads();

    // exclusive scan of hist -> binStart (warp-shfl hierarchical)
    int myCnt, myIncl;
    {
        myCnt = sm.b.hist[tid];
        int s = myCnt;
#pragma unroll
        for (int o = 1; o < 32; o <<= 1) {
            int t = __shfl_up_sync(0xffffffffu, s, o);
            if (lane >= o) s += t;
        }
        if (lane == 31) sm.b.iwarp[wrp] = s;
        __syncthreads();
        if (tid < 8) {
            int p = sm.b.iwarp[tid];
#pragma unroll
            for (int o = 1; o < 8; o <<= 1) {
                int t = __shfl_up_sync(0xffu, p, o);
                if (tid >= o) p += t;
            }
            sm.b.iwarp[tid] = p;
        }
        __syncthreads();
        myIncl = s + (wrp > 0 ? sm.b.iwarp[wrp - 1] : 0);
        sm.b.binStart[tid + 1] = myIncl;
        if (tid == 0) sm.b.binStart[0] = 0;
    }
    __syncthreads();

    // scatter into bins (value + precomputed exp)
    for (int i = tid; i < P_PRO; i += NTHR) {
        float v = sm.b.bufA[i];
        float e = sm.b.bufE[i];
        int b = bin_of(v, mnv, inv);
        int pos = sm.b.binStart[b] + atomicAdd(&sm.b.cnt[b], 1);
        sm.b.bufB[pos] = v;
        sm.b.bufC[pos] = e;
    }
    __syncthreads();

    // per-bin sums + joint double scan (prefExp exclusive / sufVal suffix)
    {
        int s0 = myIncl - myCnt, e0 = myIncl;
        float fe = 0.0f, fv = 0.0f;
        for (int i = s0; i < e0; i++) { fe += sm.b.bufC[i]; fv += sm.b.bufB[i]; }
        double se = (double)fe, sv = (double)fv;
        double ise = se, isv = sv;
#pragma unroll
        for (int o = 1; o < 32; o <<= 1) {
            double te = __shfl_up_sync(0xffffffffu, ise, o);
            double tv = __shfl_up_sync(0xffffffffu, isv, o);
            if (lane >= o) { ise += te; isv += tv; }
        }
        if (lane == 31) { sm.b.dwarpE[wrp] = ise; sm.b.dwarpV[wrp] = isv; }
        __syncthreads();
        if (tid < 8) {
            double pe = sm.b.dwarpE[tid], pv = sm.b.dwarpV[tid];
#pragma unroll
            for (int o = 1; o < 8; o <<= 1) {
                double te = __shfl_up_sync(0xffu, pe, o);
                double tv = __shfl_up_sync(0xffu, pv, o);
                if (tid >= o) { pe += te; pv += tv; }
            }
            sm.b.dwarpE[tid] = pe; sm.b.dwarpV[tid] = pv;
        }
        __syncthreads();
        double offE = (wrp > 0) ? sm.b.dwarpE[wrp - 1] : 0.0;
        double offV = (wrp > 0) ? sm.b.dwarpV[wrp - 1] : 0.0;
        double inclE = ise + offE, inclV = isv + offV;
        double totalV = sm.b.dwarpV[7];
        sm.b.prefExp[tid] = (float)(inclE - se);
        sm.b.sufVal[tid]  = (float)(totalV - (inclV - sv));
        if (tid == 0) sm.b.sufVal[NB] = 0.0f;
    }
    __syncthreads();

    // queries: y_atom[n,h] with precomputed (am, e^am)
    for (int n = tid; n < N_MOL; n += NTHR) {
        float2 ae = g_mol2[h][n];
        float am  = ae.x;
        float eam = ae.y;
        float t   = -am;
        int b  = bin_of(t, mnv, inv);
        int s0 = sm.b.binStart[b], e0 = sm.b.binStart[b + 1];
        float acc = eam * sm.b.prefExp[b] + sm.b.sufVal[b + 1]
                  + (float)(P_PRO - e0) * (am + 1.0f);
        for (int i = s0; i < e0; i++) {
            float v = sm.b.bufB[i];
            acc += (v <= t) ? eam * sm.b.bufC[i] : (am + 1.0f + v);
        }
        sm.b.bufA[n] = acc;   // bufA reused
    }
    __syncthreads();

    // segment sum -> g_ys
    if (tid < NGRAPH) {
        int b = tid;
        int lo = 0, hi = N_MOL;
        while (lo < hi) { int m = (lo + hi) >> 1; if (sm.b.bs[m] < b) lo = m + 1; else hi = m; }
        int s = lo;
        lo = 0; hi = N_MOL;
        while (lo < hi) { int m = (lo + hi) >> 1; if (sm.b.bs[m] < b + 1) lo = m + 1; else hi = m; }
        int e = lo;
        float acc = 0.0f;
        for (int n = s; n < e; n++) acc += sm.b.bufA[n];
        g_ys[b * HEADS + h] = acc * 0.001f;
    }
    __threadfence();
    __syncthreads();
    if (blockIdx.x != 0) {
        if (tid == 0) atomicAdd(&g_done, 1);
        return;
    }

    // ===== final MLP (block 0 after all 15 other head blocks done) =====
    if (tid == 0) {
        while (atomicAdd(&g_done, 0) < HEADS - 1) {}
        atomicExch(&g_done, 0);                // reset for next replay
        __threadfence();
    }
    __syncthreads();
    if (tid < NGRAPH) {
        float ys[HEADS];
#pragma unroll
        for (int hh = 0; hh < HEADS; hh++)
            ys[hh] = __ldcg(&g_ys[tid * HEADS + hh]);
        float o = b2[0];
#pragma unroll
        for (int j = 0; j < 2 * HEADS; j++) {
            float a = b1[j];
#pragma unroll
            for (int hh = 0; hh < HEADS; hh++)
                a += ys[hh] * W1[hh * (2 * HEADS) + j];
            float el = (a > 0.0f) ? a : (expf(a) - 1.0f);
            o += el * W2[j];
        }
        out[tid] = o;
    }
}

// Inputs (metadata order):
// 0 mol_feats [2048,64] f32   1 fused_feats [2048,64] f32
// 2 Wmu [128,16] f32          3 bmu [16] f32
// 4 W1 [16,32] f32            5 b1 [32] f32
// 6 W2 [32,1] f32             7 b2 [1] f32
// 8 mol_batch [2048] int64-or-int32   9 num_graphs (static B=64)
extern "C" void kernel_launch(void* const* d_in, const int* in_sizes, int n_in,
                              void* d_out, int out_size) {
    fused_kernel<<<NBLK, NTHR>>>(
        (const float*)d_in[0], (const float*)d_in[1],
        (const float*)d_in[2], (const float*)d_in[3],
        (const float*)d_in[4], (const float*)d_in[5],
        (const float*)d_in[6], (const float*)d_in[7],
        (const int*)d_in[8], (float*)d_out);
}